// round 1
// baseline (speedup 1.0000x reference)
#include <cuda_runtime.h>

#define N_GRAPH_C 4096
#define NPG_C 32
#define N_NODES_C (N_GRAPH_C*NPG_C)     // 131072
#define N_EDGES_C (N_NODES_C*16)        // 2097152

#define INV_SQRT3_C 0.5773502691896258f
#define INV_SQRT2_C 0.7071067811865476f

// ---------------- scratch (persistent device globals; re-zeroed every launch) ----------------
// acc1: layer1 segment sums: [N][16] floats: [0..3]=f0, [4..15]=f1[c][m] (c*3+m)
// acc2: layer2 segment sums: [N][44] floats:
//   [0..3]=p00_0, [4..7]=p11_0, [8..19]=p01_1[c*3+m], [20..31]=p10_1, [32..43]=p11_1
// acc3: layer3 segment sums: [N][8]: [0..3]=q00, [4..7]=q11
// feats*: gated node features: [N][16]: [0..3]=l0, [4..15]=l1[c*3+m]
__device__ float4 g_acc1[N_NODES_C*4];
__device__ float4 g_acc2[N_NODES_C*11];
__device__ float4 g_acc3[N_NODES_C*2];
__device__ float4 g_feats1[N_NODES_C*4];
__device__ float4 g_feats2[N_NODES_C*4];
__device__ float4 g_nodeout[N_NODES_C];

// ---------------- helpers ----------------
__device__ __forceinline__ void red_v4(float4* p, float a, float b, float c, float d){
  asm volatile("red.global.add.v4.f32 [%0], {%1,%2,%3,%4};"
               :: "l"(p), "f"(a), "f"(b), "f"(c), "f"(d) : "memory");
}
__device__ __forceinline__ float siluf(float x){ return x / (1.f + __expf(-x)); }
__device__ __forceinline__ float sigmf(float x){ return 1.f / (1.f + __expf(-x)); }

enum { MSG_SCALAR=0, MSG_VECU=1, MSG_VECX1=2, MSG_DOT=3, MSG_CROSS=4 };

// ---------------- zero accumulators ----------------
__global__ void zero_kernel(){
  const int T1 = N_NODES_C*4;
  const int T2 = T1 + N_NODES_C*11;
  const int T3 = T2 + N_NODES_C*2;
  float4 z = make_float4(0.f,0.f,0.f,0.f);
  int stride = gridDim.x*blockDim.x;
  for (int i = blockIdx.x*blockDim.x + threadIdx.x; i < T3; i += stride){
    if (i < T1)       g_acc1[i] = z;
    else if (i < T2)  g_acc2[i - T1] = z;
    else              g_acc3[i - T2] = z;
  }
}

// ---------------- edge kernel (one radial p per instantiation) ----------------
// SRC: 0 = layer1 (x0 = w_si1 * node_feat[s]), 1 = g_feats1, 2 = g_feats2
// DST: 1/2/3 -> g_acc1/g_acc2/g_acc3 ; SLOT = starting float4 slot in the row
template<int P, int MSG, int SRC, int DST, int SLOT>
__global__ __launch_bounds__(128)
void edge_kernel(const float* __restrict__ pos, const float* __restrict__ nf,
                 const int* __restrict__ snd, const int* __restrict__ rcv,
                 const float* __restrict__ wsi1,
                 const float* __restrict__ rw1, const float* __restrict__ rb1,
                 const float* __restrict__ rw2, const float* __restrict__ rb2)
{
  constexpr int STRIDE4 = (DST==1) ? 4 : ((DST==2) ? 11 : 2);
  float4* acc = (DST==1) ? g_acc1 : ((DST==2) ? g_acc2 : g_acc3);
  const float4* feats = (SRC==2) ? g_feats2 : g_feats1;

  // radial-MLP weights for this p, resident in registers for the whole loop
  float W1[64], W2[32], B1[8], B2[4];
  #pragma unroll
  for (int i=0;i<64;i++) W1[i] = __ldg(rw1 + P*64 + i);
  #pragma unroll
  for (int i=0;i<32;i++) W2[i] = __ldg(rw2 + P*32 + i);
  #pragma unroll
  for (int i=0;i<8;i++)  B1[i] = __ldg(rb1 + P*8 + i);
  #pragma unroll
  for (int i=0;i<4;i++)  B2[i] = __ldg(rb2 + P*4 + i);
  float ws0=0.f, ws1=0.f, ws2=0.f, ws3=0.f;
  if (SRC==0){ ws0=__ldg(wsi1+0); ws1=__ldg(wsi1+1); ws2=__ldg(wsi1+2); ws3=__ldg(wsi1+3); }

  int stride = gridDim.x*blockDim.x;
  for (int e = blockIdx.x*blockDim.x + threadIdx.x; e < N_EDGES_C; e += stride){
    int s = __ldg(snd+e);
    int r = __ldg(rcv+e);
    float ax = __ldg(pos+3*s+0), ay = __ldg(pos+3*s+1), az = __ldg(pos+3*s+2);
    float bx = __ldg(pos+3*r+0), by = __ldg(pos+3*r+1), bz = __ldg(pos+3*r+2);
    float dx = bx-ax, dy = by-ay, dz = bz-az;

    // gather sender features (issued early to overlap with MLP)
    float x0[4]; float x1[12];
    if (SRC==0){
      float nv = __ldg(nf + s);
      x0[0]=ws0*nv; x0[1]=ws1*nv; x0[2]=ws2*nv; x0[3]=ws3*nv;
    } else if (MSG==MSG_SCALAR || MSG==MSG_VECU){
      float4 t = __ldg(feats + (size_t)s*4);
      x0[0]=t.x; x0[1]=t.y; x0[2]=t.z; x0[3]=t.w;
    } else {
      float4 t1 = __ldg(feats + (size_t)s*4 + 1);
      float4 t2 = __ldg(feats + (size_t)s*4 + 2);
      float4 t3 = __ldg(feats + (size_t)s*4 + 3);
      x1[0]=t1.x;  x1[1]=t1.y;  x1[2]=t1.z;  x1[3]=t1.w;
      x1[4]=t2.x;  x1[5]=t2.y;  x1[6]=t2.z;  x1[7]=t2.w;
      x1[8]=t3.x;  x1[9]=t3.y;  x1[10]=t3.z; x1[11]=t3.w;
    }

    float d2  = dx*dx + dy*dy + dz*dz;
    float d   = sqrtf(d2);
    float inv = 1.f / fmaxf(d, 1e-9f);
    float ux = dx*inv, uy = dy*inv, uz = dz*inv;

    // rbf -> hidden (relu) -> R[4]
    float rbf[8];
    #pragma unroll
    for (int k=0;k<8;k++){ float t = d - 0.5f*(float)k; rbf[k] = __expf(-4.f*t*t); }
    float h[8];
    #pragma unroll
    for (int j=0;j<8;j++){
      float a = B1[j];
      #pragma unroll
      for (int b=0;b<8;b++) a = fmaf(rbf[b], W1[b*8+j], a);
      h[j] = fmaxf(a, 0.f);
    }
    float R[4];
    #pragma unroll
    for (int c=0;c<4;c++){
      float a = B2[c];
      #pragma unroll
      for (int j=0;j<8;j++) a = fmaf(h[j], W2[j*4+c], a);
      R[c] = a;
    }

    float4* dst = acc + (size_t)r*STRIDE4 + SLOT;
    if (MSG==MSG_SCALAR){
      red_v4(dst, R[0]*x0[0], R[1]*x0[1], R[2]*x0[2], R[3]*x0[3]);
    } else if (MSG==MSG_DOT){
      float m[4];
      #pragma unroll
      for (int c=0;c<4;c++){
        float dt = x1[c*3]*ux + x1[c*3+1]*uy + x1[c*3+2]*uz;
        m[c] = R[c]*dt*INV_SQRT3_C;
      }
      red_v4(dst, m[0], m[1], m[2], m[3]);
    } else {
      float m[12];
      if (MSG==MSG_VECU){
        #pragma unroll
        for (int c=0;c<4;c++){
          float b = R[c]*x0[c];
          m[c*3+0]=b*ux; m[c*3+1]=b*uy; m[c*3+2]=b*uz;
        }
      } else if (MSG==MSG_VECX1){
        #pragma unroll
        for (int c=0;c<4;c++){
          m[c*3+0]=R[c]*x1[c*3+0]; m[c*3+1]=R[c]*x1[c*3+1]; m[c*3+2]=R[c]*x1[c*3+2];
        }
      } else { // MSG_CROSS: cross(x1[c], u)
        #pragma unroll
        for (int c=0;c<4;c++){
          float a0=x1[c*3], a1=x1[c*3+1], a2=x1[c*3+2];
          float c0 = a1*uz - a2*uy;
          float c1 = a2*ux - a0*uz;
          float c2 = a0*uy - a1*ux;
          float sc = R[c]*INV_SQRT2_C;
          m[c*3+0]=sc*c0; m[c*3+1]=sc*c1; m[c*3+2]=sc*c2;
        }
      }
      red_v4(dst+0, m[0], m[1], m[2],  m[3]);
      red_v4(dst+1, m[4], m[5], m[6],  m[7]);
      red_v4(dst+2, m[8], m[9], m[10], m[11]);
    }
  }
}

// ---------------- node kernels ----------------
__global__ void node1_kernel(const float* __restrict__ w20, const float* __restrict__ w21){
  int n = blockIdx.x*blockDim.x + threadIdx.x;
  if (n >= N_NODES_C) return;
  float4 v0 = g_acc1[(size_t)n*4+0];
  float4 v1 = g_acc1[(size_t)n*4+1];
  float4 v2 = g_acc1[(size_t)n*4+2];
  float4 v3 = g_acc1[(size_t)n*4+3];
  float f0[4]  = {v0.x,v0.y,v0.z,v0.w};
  float f1[12] = {v1.x,v1.y,v1.z,v1.w, v2.x,v2.y,v2.z,v2.w, v3.x,v3.y,v3.z,v3.w};
  float o0[4];
  #pragma unroll
  for (int o=0;o<4;o++){
    float sAcc = 0.f;
    #pragma unroll
    for (int i=0;i<4;i++) sAcc = fmaf(__ldg(w20+o*4+i), f0[i], sAcc);
    o0[o] = siluf(sAcc);
  }
  float o1[12];
  #pragma unroll
  for (int o=0;o<4;o++){
    float y0=0.f,y1=0.f,y2=0.f;
    #pragma unroll
    for (int i=0;i<4;i++){
      float w = __ldg(w21+o*4+i);
      y0 = fmaf(w, f1[i*3+0], y0);
      y1 = fmaf(w, f1[i*3+1], y1);
      y2 = fmaf(w, f1[i*3+2], y2);
    }
    float nrm = sqrtf(y0*y0+y1*y1+y2*y2);
    float sg = sigmf(nrm);
    o1[o*3+0]=y0*sg; o1[o*3+1]=y1*sg; o1[o*3+2]=y2*sg;
  }
  g_feats1[(size_t)n*4+0] = make_float4(o0[0],o0[1],o0[2],o0[3]);
  g_feats1[(size_t)n*4+1] = make_float4(o1[0],o1[1],o1[2],o1[3]);
  g_feats1[(size_t)n*4+2] = make_float4(o1[4],o1[5],o1[6],o1[7]);
  g_feats1[(size_t)n*4+3] = make_float4(o1[8],o1[9],o1[10],o1[11]);
}

__global__ void node2_kernel(const float* __restrict__ w30, const float* __restrict__ w31){
  int n = blockIdx.x*blockDim.x + threadIdx.x;
  if (n >= N_NODES_C) return;
  const float4* a = g_acc2 + (size_t)n*11;
  float4 t0 = a[0], t1 = a[1];
  float f0[8] = {t0.x,t0.y,t0.z,t0.w, t1.x,t1.y,t1.z,t1.w};
  float f1[36];
  #pragma unroll
  for (int q=0;q<9;q++){
    float4 t = a[2+q];
    f1[q*4+0]=t.x; f1[q*4+1]=t.y; f1[q*4+2]=t.z; f1[q*4+3]=t.w;
  }
  float o0[4];
  #pragma unroll
  for (int o=0;o<4;o++){
    float sAcc = 0.f;
    #pragma unroll
    for (int i=0;i<8;i++) sAcc = fmaf(__ldg(w30+o*8+i), f0[i], sAcc);
    o0[o] = siluf(sAcc);
  }
  float o1[12];
  #pragma unroll
  for (int o=0;o<4;o++){
    float y0=0.f,y1=0.f,y2=0.f;
    #pragma unroll
    for (int i=0;i<12;i++){
      float w = __ldg(w31+o*12+i);
      y0 = fmaf(w, f1[i*3+0], y0);
      y1 = fmaf(w, f1[i*3+1], y1);
      y2 = fmaf(w, f1[i*3+2], y2);
    }
    float nrm = sqrtf(y0*y0+y1*y1+y2*y2);
    float sg = sigmf(nrm);
    o1[o*3+0]=y0*sg; o1[o*3+1]=y1*sg; o1[o*3+2]=y2*sg;
  }
  g_feats2[(size_t)n*4+0] = make_float4(o0[0],o0[1],o0[2],o0[3]);
  g_feats2[(size_t)n*4+1] = make_float4(o1[0],o1[1],o1[2],o1[3]);
  g_feats2[(size_t)n*4+2] = make_float4(o1[4],o1[5],o1[6],o1[7]);
  g_feats2[(size_t)n*4+3] = make_float4(o1[8],o1[9],o1[10],o1[11]);
}

__global__ void node3_kernel(const float* __restrict__ w4){
  int n = blockIdx.x*blockDim.x + threadIdx.x;
  if (n >= N_NODES_C) return;
  float4 t0 = g_acc3[(size_t)n*2+0];
  float4 t1 = g_acc3[(size_t)n*2+1];
  float f[8] = {t0.x,t0.y,t0.z,t0.w, t1.x,t1.y,t1.z,t1.w};
  float o[4];
  #pragma unroll
  for (int j=0;j<4;j++){
    float sAcc = 0.f;
    #pragma unroll
    for (int i=0;i<8;i++) sAcc = fmaf(__ldg(w4+j*8+i), f[i], sAcc);
    o[j] = siluf(sAcc);
  }
  g_nodeout[n] = make_float4(o[0],o[1],o[2],o[3]);
}

// ---------------- graph pooling + output projection ----------------
__global__ void pool_kernel(const float* __restrict__ w_out, float* __restrict__ out){
  int gw   = (blockIdx.x*blockDim.x + threadIdx.x) >> 5;   // one warp per graph
  int lane = threadIdx.x & 31;
  if (gw >= N_GRAPH_C) return;
  float4 v = g_nodeout[(size_t)gw*32 + lane];
  #pragma unroll
  for (int off=16; off; off>>=1){
    v.x += __shfl_down_sync(0xFFFFFFFFu, v.x, off);
    v.y += __shfl_down_sync(0xFFFFFFFFu, v.y, off);
    v.z += __shfl_down_sync(0xFFFFFFFFu, v.z, off);
    v.w += __shfl_down_sync(0xFFFFFFFFu, v.w, off);
  }
  if (lane == 0){
    #pragma unroll
    for (int j=0;j<8;j++){
      out[gw*8+j] = __ldg(w_out+j*4+0)*v.x + __ldg(w_out+j*4+1)*v.y
                  + __ldg(w_out+j*4+2)*v.z + __ldg(w_out+j*4+3)*v.w;
    }
  }
}

// ---------------- launch ----------------
extern "C" void kernel_launch(void* const* d_in, const int* in_sizes, int n_in,
                              void* d_out, int out_size)
{
  const float* positions = (const float*)d_in[0];
  const float* node_feat = (const float*)d_in[1];
  const float* w_si1     = (const float*)d_in[2];
  const float* w_si2_0   = (const float*)d_in[3];
  const float* w_si2_1   = (const float*)d_in[4];
  const float* w_si3_0   = (const float*)d_in[5];
  const float* w_si3_1   = (const float*)d_in[6];
  const float* w_si4     = (const float*)d_in[7];
  const float* w_out     = (const float*)d_in[8];
  const float* rad_w1    = (const float*)d_in[9];
  const float* rad_b1    = (const float*)d_in[10];
  const float* rad_w2    = (const float*)d_in[11];
  const float* rad_b2    = (const float*)d_in[12];
  const int*   senders   = (const int*)d_in[13];
  const int*   receivers = (const int*)d_in[14];
  // d_in[15] = n_node, always 32 per graph with consecutive node blocks
  float* out = (float*)d_out;

  const int EB = 4096, ET = 128;       // edge kernels: grid-stride
  const int NB = (N_NODES_C + 255)/256;

  zero_kernel<<<2048, 256>>>();

  // layer 1 (x0 = w_si1 * node_feat)
  edge_kernel<0, MSG_SCALAR, 0, 1, 0><<<EB,ET>>>(positions,node_feat,senders,receivers,w_si1,rad_w1,rad_b1,rad_w2,rad_b2);
  edge_kernel<1, MSG_VECU,   0, 1, 1><<<EB,ET>>>(positions,node_feat,senders,receivers,w_si1,rad_w1,rad_b1,rad_w2,rad_b2);
  node1_kernel<<<NB, 256>>>(w_si2_0, w_si2_1);

  // layer 2
  edge_kernel<2, MSG_SCALAR, 1, 2, 0><<<EB,ET>>>(positions,node_feat,senders,receivers,w_si1,rad_w1,rad_b1,rad_w2,rad_b2);
  edge_kernel<3, MSG_VECU,   1, 2, 2><<<EB,ET>>>(positions,node_feat,senders,receivers,w_si1,rad_w1,rad_b1,rad_w2,rad_b2);
  edge_kernel<4, MSG_VECX1,  1, 2, 5><<<EB,ET>>>(positions,node_feat,senders,receivers,w_si1,rad_w1,rad_b1,rad_w2,rad_b2);
  edge_kernel<5, MSG_DOT,    1, 2, 1><<<EB,ET>>>(positions,node_feat,senders,receivers,w_si1,rad_w1,rad_b1,rad_w2,rad_b2);
  edge_kernel<6, MSG_CROSS,  1, 2, 8><<<EB,ET>>>(positions,node_feat,senders,receivers,w_si1,rad_w1,rad_b1,rad_w2,rad_b2);
  node2_kernel<<<NB, 256>>>(w_si3_0, w_si3_1);

  // layer 3
  edge_kernel<7, MSG_SCALAR, 2, 3, 0><<<EB,ET>>>(positions,node_feat,senders,receivers,w_si1,rad_w1,rad_b1,rad_w2,rad_b2);
  edge_kernel<8, MSG_DOT,    2, 3, 1><<<EB,ET>>>(positions,node_feat,senders,receivers,w_si1,rad_w1,rad_b1,rad_w2,rad_b2);
  node3_kernel<<<NB, 256>>>(w_si4);

  // pooling + w_out
  pool_kernel<<<(N_GRAPH_C*32 + 255)/256, 256>>>(w_out, out);
}

// round 3
// speedup vs baseline: 1.9224x; 1.9224x over previous
#include <cuda_runtime.h>

#define N_GRAPH_C 4096
#define N_NODES_C 131072
#define N_EDGES_C 2097152

#define NT 16384
#define TBL_SCALE 2048.0f            // NT / 8.0
#define TBL_INV_SCALE 4.8828125e-4f  // 8.0 / NT
#define INV_SQRT3_C 0.5773502691896258f
#define INV_SQRT2_C 0.7071067811865476f

// ---------------- persistent device scratch ----------------
// Tables (rebuilt every launch from weights):
//  g_T1[k*2+0] = A0[o] = sum_c w_si2_0[o,c]*w_si1[c]*R0[c](d)   (layer1 l0, fully folded)
//  g_T1[k*2+1] = A1[o] = sum_c w_si2_1[o,c]*w_si1[c]*R1[c](d)   (layer1 l1, fully folded)
//  g_T2[k*5+{0..4}] = R2, R3, R4, R5/sqrt3, R6/sqrt2
//  g_T3[k*2+{0,1}]  = R7, R8/sqrt3
__device__ float4 g_T1[NT*2];
__device__ float4 g_T2[NT*5];
__device__ float4 g_T3[NT*2];
// Per-edge cached geometry: {ux, uy, uz, fid = d*TBL_SCALE}
__device__ float4 g_geo[N_EDGES_C];
// Accumulators (post self-interaction, pre-gate): 16,16,4 floats per node
__device__ float4 g_acc1[N_NODES_C*4];
__device__ float4 g_acc2[N_NODES_C*4];
__device__ float4 g_acc3[N_NODES_C];
// Gated features: [0..3]=l0, [4..15]=l1 (layout i*3+m)
__device__ float4 g_feats1[N_NODES_C*4];
__device__ float4 g_feats2[N_NODES_C*4];
__device__ float4 g_nodeout[N_NODES_C];

// ---------------- helpers ----------------
__device__ __forceinline__ void red_v4(float4* p, float a, float b, float c, float d){
  asm volatile("red.global.add.v4.f32 [%0], {%1,%2,%3,%4};"
               :: "l"(p), "f"(a), "f"(b), "f"(c), "f"(d) : "memory");
}
__device__ __forceinline__ float siluf(float x){ return x / (1.f + __expf(-x)); }
__device__ __forceinline__ float sigmf(float x){ return 1.f / (1.f + __expf(-x)); }
__device__ __forceinline__ float4 lerp4(float4 a, float4 b, float w){
  return make_float4(fmaf(w, b.x-a.x, a.x), fmaf(w, b.y-a.y, a.y),
                     fmaf(w, b.z-a.z, a.z), fmaf(w, b.w-a.w, a.w));
}
// decode table index/weight from cached fid (clamping identical everywhere)
__device__ __forceinline__ void tbl_decode(float fid, int& i0, float& w){
  int i = (int)fid;
  i = (i > NT-2) ? (NT-2) : i;
  i0 = i;
  w = fminf(fid - (float)i, 1.f);
}

// ---------------- zero layer-1 accumulator ----------------
__global__ void zero_acc1(){
  int i = blockIdx.x*blockDim.x + threadIdx.x;
  if (i < N_NODES_C*4) g_acc1[i] = make_float4(0.f,0.f,0.f,0.f);
}

// ---------------- build radial tables (one thread per (p, entry)) ----------------
__global__ void build_table(const float* __restrict__ rw1, const float* __restrict__ rb1,
                            const float* __restrict__ rw2, const float* __restrict__ rb2,
                            const float* __restrict__ wsi1,
                            const float* __restrict__ w20, const float* __restrict__ w21)
{
  int idx = blockIdx.x*blockDim.x + threadIdx.x;
  if (idx >= 9*NT) return;
  int p = idx / NT;
  int k = idx - p*NT;
  float d = (float)k * TBL_INV_SCALE;

  float rbf[8];
  #pragma unroll
  for (int j=0;j<8;j++){ float t = d - 0.5f*(float)j; rbf[j] = __expf(-4.f*t*t); }
  float h[8];
  #pragma unroll
  for (int j=0;j<8;j++){
    float a = __ldg(rb1 + p*8 + j);
    #pragma unroll
    for (int b=0;b<8;b++) a = fmaf(rbf[b], __ldg(rw1 + p*64 + b*8 + j), a);
    h[j] = fmaxf(a, 0.f);
  }
  float R[4];
  #pragma unroll
  for (int c=0;c<4;c++){
    float a = __ldg(rb2 + p*4 + c);
    #pragma unroll
    for (int j=0;j<8;j++) a = fmaf(h[j], __ldg(rw2 + p*32 + j*4 + c), a);
    R[c] = a;
  }

  if (p <= 1){
    const float* W = (p==0) ? w20 : w21;
    float A[4];
    #pragma unroll
    for (int o=0;o<4;o++){
      float a = 0.f;
      #pragma unroll
      for (int c=0;c<4;c++) a = fmaf(__ldg(W + o*4 + c) * __ldg(wsi1 + c), R[c], a);
      A[o] = a;
    }
    g_T1[k*2 + p] = make_float4(A[0],A[1],A[2],A[3]);
  } else if (p <= 6){
    float s = (p==5) ? INV_SQRT3_C : ((p==6) ? INV_SQRT2_C : 1.f);
    g_T2[k*5 + (p-2)] = make_float4(R[0]*s, R[1]*s, R[2]*s, R[3]*s);
  } else {
    float s = (p==8) ? INV_SQRT3_C : 1.f;
    g_T3[k*2 + (p-7)] = make_float4(R[0]*s, R[1]*s, R[2]*s, R[3]*s);
  }
}

// ---------------- layer 1 edge kernel (computes + caches geometry) ----------------
__global__ __launch_bounds__(256)
void edge1_kernel(const float* __restrict__ pos, const float* __restrict__ nf,
                  const int* __restrict__ snd, const int* __restrict__ rcv)
{
  int stride = gridDim.x*blockDim.x;
  for (int e = blockIdx.x*blockDim.x + threadIdx.x; e < N_EDGES_C; e += stride){
    int s = __ldg(snd+e), r = __ldg(rcv+e);
    float nv = __ldg(nf + s);
    float ax=__ldg(pos+3*s), ay=__ldg(pos+3*s+1), az=__ldg(pos+3*s+2);
    float bx=__ldg(pos+3*r), by=__ldg(pos+3*r+1), bz=__ldg(pos+3*r+2);
    float dx=bx-ax, dy=by-ay, dz=bz-az;
    float d = sqrtf(dx*dx + dy*dy + dz*dz);
    float inv = 1.f / fmaxf(d, 1e-9f);
    float ux = dx*inv, uy = dy*inv, uz = dz*inv;
    float fid = d * TBL_SCALE;
    g_geo[e] = make_float4(ux, uy, uz, fid);

    int i0; float w; tbl_decode(fid, i0, w);
    const float4* t = &g_T1[(size_t)i0*2];
    float4 A0 = lerp4(__ldg(t+0), __ldg(t+2), w);
    float4 A1 = lerp4(__ldg(t+1), __ldg(t+3), w);
    float4* dst = &g_acc1[(size_t)r*4];
    red_v4(dst, nv*A0.x, nv*A0.y, nv*A0.z, nv*A0.w);
    float t0=nv*A1.x, t1=nv*A1.y, t2=nv*A1.z, t3=nv*A1.w;
    red_v4(dst+1, t0*ux, t0*uy, t0*uz, t1*ux);
    red_v4(dst+2, t1*uy, t1*uz, t2*ux, t2*uy);
    red_v4(dst+3, t2*uz, t3*ux, t3*uy, t3*uz);
  }
}

// ---------------- layer 2 edge kernel ----------------
__global__ __launch_bounds__(256)
void edge2_kernel(const int* __restrict__ snd, const int* __restrict__ rcv,
                  const float* __restrict__ w30, const float* __restrict__ w31)
{
  float W0[32];
  #pragma unroll
  for (int i=0;i<32;i++) W0[i] = __ldg(w30+i);
  float W1[48];
  #pragma unroll
  for (int i=0;i<48;i++) W1[i] = __ldg(w31+i);

  int stride = gridDim.x*blockDim.x;
  for (int e = blockIdx.x*blockDim.x + threadIdx.x; e < N_EDGES_C; e += stride){
    int s = __ldg(snd+e), r = __ldg(rcv+e);
    float4 geo = __ldg(&g_geo[e]);
    float ux = geo.x, uy = geo.y, uz = geo.z;
    int i0; float w; tbl_decode(geo.w, i0, w);

    float4 f0v = __ldg(&g_feats1[(size_t)s*4]);
    float4 fa  = __ldg(&g_feats1[(size_t)s*4+1]);
    float4 fb  = __ldg(&g_feats1[(size_t)s*4+2]);
    float4 fc  = __ldg(&g_feats1[(size_t)s*4+3]);
    float x0[4]  = {f0v.x,f0v.y,f0v.z,f0v.w};
    float x1[12] = {fa.x,fa.y,fa.z,fa.w, fb.x,fb.y,fb.z,fb.w, fc.x,fc.y,fc.z,fc.w};

    const float4* t = &g_T2[(size_t)i0*5];
    float4 r2 = lerp4(__ldg(t+0), __ldg(t+5), w);
    float4 r3 = lerp4(__ldg(t+1), __ldg(t+6), w);
    float4 r4 = lerp4(__ldg(t+2), __ldg(t+7), w);
    float4 r5 = lerp4(__ldg(t+3), __ldg(t+8), w);   // pre-scaled 1/sqrt3
    float4 r6 = lerp4(__ldg(t+4), __ldg(t+9), w);   // pre-scaled 1/sqrt2
    float R2[4]={r2.x,r2.y,r2.z,r2.w}, R3[4]={r3.x,r3.y,r3.z,r3.w};
    float R4[4]={r4.x,r4.y,r4.z,r4.w}, R5[4]={r5.x,r5.y,r5.z,r5.w};
    float R6[4]={r6.x,r6.y,r6.z,r6.w};

    float dot_[4];
    #pragma unroll
    for (int i=0;i<4;i++)
      dot_[i] = x1[i*3]*ux + x1[i*3+1]*uy + x1[i*3+2]*uz;

    // l0: W0 @ [R2*x0 ; R5*dot/sqrt3]
    float ma[4], mb[4];
    #pragma unroll
    for (int i=0;i<4;i++){ ma[i] = R2[i]*x0[i]; mb[i] = R5[i]*dot_[i]; }
    float o0[4];
    #pragma unroll
    for (int o=0;o<4;o++){
      float a = 0.f;
      #pragma unroll
      for (int i=0;i<4;i++){
        a = fmaf(W0[o*8+i],   ma[i], a);
        a = fmaf(W0[o*8+4+i], mb[i], a);
      }
      o0[o] = a;
    }
    float4* dst = &g_acc2[(size_t)r*4];
    red_v4(dst, o0[0], o0[1], o0[2], o0[3]);

    // l1: W1 @ [R3*x0*u ; R4*x1 ; R6*cross(x1,u)/sqrt2]
    float c3[4], e4[12], e6[12];
    #pragma unroll
    for (int i=0;i<4;i++){
      c3[i] = R3[i]*x0[i];
      e4[i*3+0]=R4[i]*x1[i*3+0]; e4[i*3+1]=R4[i]*x1[i*3+1]; e4[i*3+2]=R4[i]*x1[i*3+2];
      e6[i*3+0]=R6[i]*x1[i*3+0]; e6[i*3+1]=R6[i]*x1[i*3+1]; e6[i*3+2]=R6[i]*x1[i*3+2];
    }
    float o1[12];
    #pragma unroll
    for (int o=0;o<4;o++){
      float ta=0.f, zx=0.f, zy=0.f, zz=0.f, yx=0.f, yy=0.f, yz=0.f;
      #pragma unroll
      for (int i=0;i<4;i++){
        ta = fmaf(W1[o*12+i], c3[i], ta);
        float w4 = W1[o*12+4+i], w6 = W1[o*12+8+i];
        zx = fmaf(w4, e4[i*3+0], zx); zy = fmaf(w4, e4[i*3+1], zy); zz = fmaf(w4, e4[i*3+2], zz);
        yx = fmaf(w6, e6[i*3+0], yx); yy = fmaf(w6, e6[i*3+1], yy); yz = fmaf(w6, e6[i*3+2], yz);
      }
      float cx = yy*uz - yz*uy;
      float cy = yz*ux - yx*uz;
      float cz = yx*uy - yy*ux;
      o1[o*3+0] = fmaf(ta, ux, zx + cx);
      o1[o*3+1] = fmaf(ta, uy, zy + cy);
      o1[o*3+2] = fmaf(ta, uz, zz + cz);
    }
    red_v4(dst+1, o1[0], o1[1], o1[2],  o1[3]);
    red_v4(dst+2, o1[4], o1[5], o1[6],  o1[7]);
    red_v4(dst+3, o1[8], o1[9], o1[10], o1[11]);
  }
}

// ---------------- layer 3 edge kernel ----------------
__global__ __launch_bounds__(256)
void edge3_kernel(const int* __restrict__ snd, const int* __restrict__ rcv,
                  const float* __restrict__ w4)
{
  float W4[32];
  #pragma unroll
  for (int i=0;i<32;i++) W4[i] = __ldg(w4+i);

  int stride = gridDim.x*blockDim.x;
  for (int e = blockIdx.x*blockDim.x + threadIdx.x; e < N_EDGES_C; e += stride){
    int s = __ldg(snd+e), r = __ldg(rcv+e);
    float4 geo = __ldg(&g_geo[e]);
    float ux = geo.x, uy = geo.y, uz = geo.z;
    int i0; float w; tbl_decode(geo.w, i0, w);

    float4 f0v = __ldg(&g_feats2[(size_t)s*4]);
    float4 fa  = __ldg(&g_feats2[(size_t)s*4+1]);
    float4 fb  = __ldg(&g_feats2[(size_t)s*4+2]);
    float4 fc  = __ldg(&g_feats2[(size_t)s*4+3]);
    float x0[4]  = {f0v.x,f0v.y,f0v.z,f0v.w};
    float x1[12] = {fa.x,fa.y,fa.z,fa.w, fb.x,fb.y,fb.z,fb.w, fc.x,fc.y,fc.z,fc.w};

    const float4* t = &g_T3[(size_t)i0*2];
    float4 r7 = lerp4(__ldg(t+0), __ldg(t+2), w);
    float4 r8 = lerp4(__ldg(t+1), __ldg(t+3), w);  // pre-scaled 1/sqrt3
    float R7[4]={r7.x,r7.y,r7.z,r7.w}, R8[4]={r8.x,r8.y,r8.z,r8.w};

    float dot_[4];
    #pragma unroll
    for (int i=0;i<4;i++)
      dot_[i] = x1[i*3]*ux + x1[i*3+1]*uy + x1[i*3+2]*uz;

    float o[4];
    #pragma unroll
    for (int oo=0;oo<4;oo++){
      float a = 0.f;
      #pragma unroll
      for (int i=0;i<4;i++){
        a = fmaf(W4[oo*8+i],   R7[i]*x0[i],   a);
        a = fmaf(W4[oo*8+4+i], R8[i]*dot_[i], a);
      }
      o[oo] = a;
    }
    red_v4(&g_acc3[r], o[0], o[1], o[2], o[3]);
  }
}

// ---------------- node gating (layers 1 & 2); zeroes next accumulator ----------------
template<int L>
__global__ void node_gate_kernel(){
  int n = blockIdx.x*blockDim.x + threadIdx.x;
  if (n >= N_NODES_C) return;
  const float4* acc = (L==1) ? g_acc1 : g_acc2;
  float4* fe = (L==1) ? g_feats1 : g_feats2;
  float4 s0 = acc[(size_t)n*4+0];
  float4 s1 = acc[(size_t)n*4+1];
  float4 s2 = acc[(size_t)n*4+2];
  float4 s3 = acc[(size_t)n*4+3];
  float f1[12] = {s1.x,s1.y,s1.z,s1.w, s2.x,s2.y,s2.z,s2.w, s3.x,s3.y,s3.z,s3.w};
  float o1[12];
  #pragma unroll
  for (int o=0;o<4;o++){
    float a=f1[o*3], b=f1[o*3+1], c=f1[o*3+2];
    float nrm = sqrtf(a*a + b*b + c*c);
    float sg = sigmf(nrm);
    o1[o*3+0]=a*sg; o1[o*3+1]=b*sg; o1[o*3+2]=c*sg;
  }
  fe[(size_t)n*4+0] = make_float4(siluf(s0.x), siluf(s0.y), siluf(s0.z), siluf(s0.w));
  fe[(size_t)n*4+1] = make_float4(o1[0],o1[1],o1[2],o1[3]);
  fe[(size_t)n*4+2] = make_float4(o1[4],o1[5],o1[6],o1[7]);
  fe[(size_t)n*4+3] = make_float4(o1[8],o1[9],o1[10],o1[11]);
  // zero the accumulator used by the NEXT edge kernel
  float4 z = make_float4(0.f,0.f,0.f,0.f);
  if (L==1){
    g_acc2[(size_t)n*4+0]=z; g_acc2[(size_t)n*4+1]=z;
    g_acc2[(size_t)n*4+2]=z; g_acc2[(size_t)n*4+3]=z;
  } else {
    g_acc3[n] = z;
  }
}

// ---------------- layer 3 node (silu gate only) ----------------
__global__ void node3_kernel(){
  int n = blockIdx.x*blockDim.x + threadIdx.x;
  if (n >= N_NODES_C) return;
  float4 a = g_acc3[n];
  g_nodeout[n] = make_float4(siluf(a.x), siluf(a.y), siluf(a.z), siluf(a.w));
}

// ---------------- graph pooling + output projection ----------------
__global__ void pool_kernel(const float* __restrict__ w_out, float* __restrict__ out){
  int gw   = (blockIdx.x*blockDim.x + threadIdx.x) >> 5;
  int lane = threadIdx.x & 31;
  if (gw >= N_GRAPH_C) return;
  float4 v = g_nodeout[(size_t)gw*32 + lane];
  #pragma unroll
  for (int off=16; off; off>>=1){
    v.x += __shfl_down_sync(0xFFFFFFFFu, v.x, off);
    v.y += __shfl_down_sync(0xFFFFFFFFu, v.y, off);
    v.z += __shfl_down_sync(0xFFFFFFFFu, v.z, off);
    v.w += __shfl_down_sync(0xFFFFFFFFu, v.w, off);
  }
  if (lane == 0){
    #pragma unroll
    for (int j=0;j<8;j++){
      out[gw*8+j] = __ldg(w_out+j*4+0)*v.x + __ldg(w_out+j*4+1)*v.y
                  + __ldg(w_out+j*4+2)*v.z + __ldg(w_out+j*4+3)*v.w;
    }
  }
}

// ---------------- launch ----------------
extern "C" void kernel_launch(void* const* d_in, const int* in_sizes, int n_in,
                              void* d_out, int out_size)
{
  const float* positions = (const float*)d_in[0];
  const float* node_feat = (const float*)d_in[1];
  const float* w_si1     = (const float*)d_in[2];
  const float* w_si2_0   = (const float*)d_in[3];
  const float* w_si2_1   = (const float*)d_in[4];
  const float* w_si3_0   = (const float*)d_in[5];
  const float* w_si3_1   = (const float*)d_in[6];
  const float* w_si4     = (const float*)d_in[7];
  const float* w_out     = (const float*)d_in[8];
  const float* rad_w1    = (const float*)d_in[9];
  const float* rad_b1    = (const float*)d_in[10];
  const float* rad_w2    = (const float*)d_in[11];
  const float* rad_b2    = (const float*)d_in[12];
  const int*   senders   = (const int*)d_in[13];
  const int*   receivers = (const int*)d_in[14];
  float* out = (float*)d_out;

  const int EB = 1024, ET = 256;     // edge kernels: grid-stride, 8 edges/thread
  const int NB = N_NODES_C / 256;

  zero_acc1<<<N_NODES_C*4/256, 256>>>();
  build_table<<<(9*NT + 127)/128, 128>>>(rad_w1, rad_b1, rad_w2, rad_b2,
                                         w_si1, w_si2_0, w_si2_1);

  edge1_kernel<<<EB, ET>>>(positions, node_feat, senders, receivers);
  node_gate_kernel<1><<<NB, 256>>>();

  edge2_kernel<<<EB, ET>>>(senders, receivers, w_si3_0, w_si3_1);
  node_gate_kernel<2><<<NB, 256>>>();

  edge3_kernel<<<EB, ET>>>(senders, receivers, w_si4);
  node3_kernel<<<NB, 256>>>();

  pool_kernel<<<(N_GRAPH_C*32)/256, 256>>>(w_out, out);
}